// round 17
// baseline (speedup 1.0000x reference)
#include <cuda_runtime.h>
#include <cuda_fp16.h>
#include <math.h>
#include <stdint.h>

// Problem constants
#define BB 4
#define SS 4096
#define DD 1024
#define HH 8
#define KK 128
#define PP 32
#define NROW (BB*SS)          // 16384
#define PI_F 3.14159265358979f

// ---------------------------------------------------------------------------
// Device-global scratch (no allocations allowed)
// ---------------------------------------------------------------------------
__device__ __half g_xh[(size_t)NROW * DD];   // fp16 x
__device__ __half g_hh[(size_t)NROW * DD];   // fp16 heads (GEMM1 out)
__device__ __half g_mh[(size_t)NROW * DD];   // fp16 mixed (GEMM2 A)
__device__ __half g_wh1[DD * DD];            // W_proj fp16
__device__ __half g_wh2[DD * DD];            // out_W fp16
__device__ float g_heads[(size_t)NROW * DD]; // y fp32 (GEMM2 out)
__device__ float g_part[64 * DD];            // per-row-tile column sums
__device__ float g_coef[BB * HH * HH];       // 0.1/(1+imp), zero diag

__device__ __forceinline__ uint32_t smem_to_u32(const void* smem_ptr) {
    uint32_t addr;
    asm("{ .reg .u64 tmp; cvta.to.shared.u64 tmp, %1; cvt.u32.u64 %0, tmp; }"
        : "=r"(addr) : "l"(smem_ptr));
    return addr;
}

__device__ __forceinline__ void cpasync16(uint32_t dst, const void* src) {
    asm volatile("cp.async.cg.shared.global [%0], [%1], 16;"
                 :: "r"(dst), "l"(src) : "memory");
}

#define CP_COMMIT() asm volatile("cp.async.commit_group;" ::: "memory")
#define CP_WAIT2()  asm volatile("cp.async.wait_group 2;" ::: "memory")

#define LDSM4(r, addr) \
    asm volatile("ldmatrix.sync.aligned.m8n8.x4.shared.b16 {%0,%1,%2,%3}, [%4];" \
        : "=r"((r)[0]), "=r"((r)[1]), "=r"((r)[2]), "=r"((r)[3]) : "r"(addr))

__device__ __forceinline__ void mma_fp16(float* c, const uint32_t* a,
                                         uint32_t b0, uint32_t b1) {
    asm volatile(
        "mma.sync.aligned.m16n8k16.row.col.f32.f16.f16.f32 "
        "{%0,%1,%2,%3}, {%4,%5,%6,%7}, {%8,%9}, {%0,%1,%2,%3};"
        : "+f"(c[0]), "+f"(c[1]), "+f"(c[2]), "+f"(c[3])
        : "r"(a[0]), "r"(a[1]), "r"(a[2]), "r"(a[3]), "r"(b0), "r"(b1));
}

// ---------------------------------------------------------------------------
// fp16 conversion: x, W_proj, out_W -> single fp16.  ONE launch.
// ---------------------------------------------------------------------------
#define NBX (NROW * DD / 4 / 256)   // 4096 blocks for x
#define NBW (DD * DD / 4 / 256)     // 1024 blocks per weight
__global__ void convert_all(const float* __restrict__ x,
                            const float* __restrict__ w1,
                            const float* __restrict__ w2)
{
    int blk = blockIdx.x;
    const float* src;
    __half* hp;
    int i;
    if (blk < NBX) {
        src = x;  hp = g_xh;  i = blk * 256 + threadIdx.x;
    } else if (blk < NBX + NBW) {
        src = w1; hp = g_wh1; i = (blk - NBX) * 256 + threadIdx.x;
    } else {
        src = w2; hp = g_wh2; i = (blk - NBX - NBW) * 256 + threadIdx.x;
    }
    float4 v = ((const float4*)src)[i];
    ((__half2*)hp)[2 * i + 0] = __floats2half2_rn(v.x, v.y);
    ((__half2*)hp)[2 * i + 1] = __floats2half2_rn(v.z, v.w);
}

// ---------------------------------------------------------------------------
// mma.sync GEMM: C[n,m] = sum_d A[n,d]*W[m,d], single-pass fp16.
// CTA tile 256(M)x128(N), BK=32, 256 threads (8 warps 4x2, warp 64x64),
// 3-stage cp.async pipeline, 1 CTA/SM.  Halves L2 supply per MMA-unit vs
// 128x128 (chip LTS demand ~3KB/cyc << 6.3KB/cyc cap).
//   MODE 0: A = x,     epi: * cos(freq[m]*pi) -> g_hh (fp16), colsum -> g_part
//   MODE 1: A = mixed, epi: + out_b[m] + x[n,m]           -> g_heads (fp32)
// SMEM rows padded to 80B -> conflict-free ldmatrix phases.
// ---------------------------------------------------------------------------
#define RSB   80                 // row stride bytes (32 fp16 + 16B pad)
#define AOPB  (256 * RSB)        // 20480 bytes A tile
#define BOPB  (128 * RSB)        // 10240 bytes B tile
#define STGB  (AOPB + BOPB)      // 30720 per stage
#define NSTG  3
#define GEMM_SMEM (NSTG * STGB)  // 92160

template<int MODE>
__global__ __launch_bounds__(256, 1)
void gemm_mma(const float* __restrict__ xres, const float* __restrict__ aux)
{
    extern __shared__ char sm[];
    const uint32_t sb = smem_to_u32(sm);
    const int tid = threadIdx.x;
    const int lane = tid & 31;
    const int wid = tid >> 5;        // 0..7
    const int wm = wid & 3;          // 4 M groups of 64
    const int wn = wid >> 2;         // 2 N groups of 64
    const int bc = blockIdx.x;       // col tile 0..7
    const int br = blockIdx.y;       // row tile 0..63

    const __half* A = (MODE == 0) ? g_xh : g_mh;
    const __half* B = (MODE == 0) ? g_wh1 : g_wh2;

    // ---- loader mapping: A 4x16B + B 2x16B per thread per stage ----
    const int r4  = tid >> 2;       // 0..63
    const int seg = tid & 3;
    const __half* gA = A + (size_t)(br * 256 + r4) * DD + seg * 8;
    const __half* gB = B + (size_t)(bc * 128 + r4) * DD + seg * 8;
    const uint32_t sload = sb + r4 * RSB + seg * 16;

    // ---- ldmatrix source offsets (within a stage) ----
    const uint32_t aoff = (uint32_t)((wm * 64 + (lane & 15)) * RSB + (lane >> 4) * 16);
    const uint32_t boff = (uint32_t)((wn * 64 + ((lane >> 4) << 3) + (lane & 7)) * RSB
                                     + ((lane >> 3) & 1) * 16);

    float acc[4][8][4];
#pragma unroll
    for (int i = 0; i < 4; i++)
#pragma unroll
        for (int j = 0; j < 8; j++)
#pragma unroll
            for (int q = 0; q < 4; q++) acc[i][j][q] = 0.f;

    // ---- prologue: fill 3 stages ----
#pragma unroll
    for (int s = 0; s < NSTG; s++) {
#pragma unroll
        for (int h = 0; h < 4; h++)      // A: 256 rows
            cpasync16(sload + s * STGB + h * (64 * RSB),
                      gA + (size_t)h * 64 * DD + s * 32);
#pragma unroll
        for (int h = 0; h < 2; h++)      // B: 128 rows
            cpasync16(sload + s * STGB + AOPB + h * (64 * RSB),
                      gB + (size_t)h * 64 * DD + s * 32);
        CP_COMMIT();
    }

    // ---- main loop over 32 k-chunks ----
    for (int c = 0; c < 32; c++) {
        CP_WAIT2();
        __syncthreads();
        const uint32_t stg = sb + (c % NSTG) * STGB;

#pragma unroll
        for (int kk = 0; kk < 2; kk++) {
            uint32_t ah[4][4];
#pragma unroll
            for (int mi = 0; mi < 4; mi++)
                LDSM4(ah[mi], stg + aoff + mi * (16 * RSB) + kk * 32);
#pragma unroll
            for (int g = 0; g < 4; g++) {
                uint32_t bh[4];
                LDSM4(bh, stg + AOPB + boff + g * (16 * RSB) + kk * 32);
#pragma unroll
                for (int mi = 0; mi < 4; mi++)
#pragma unroll
                    for (int nl = 0; nl < 2; nl++) {
                        const int i0 = nl * 2;
                        mma_fp16(acc[mi][g * 2 + nl], ah[mi], bh[i0], bh[i0 + 1]);
                    }
            }
        }
        __syncthreads();
        if (c + NSTG < 32) {
            const uint32_t dst = sload + (c % NSTG) * STGB;
#pragma unroll
            for (int h = 0; h < 4; h++)
                cpasync16(dst + h * (64 * RSB),
                          gA + (size_t)h * 64 * DD + (c + NSTG) * 32);
#pragma unroll
            for (int h = 0; h < 2; h++)
                cpasync16(dst + AOPB + h * (64 * RSB),
                          gB + (size_t)h * 64 * DD + (c + NSTG) * 32);
        }
        CP_COMMIT();
    }

    // ---- epilogue ----
    const int mbase = br * 256 + wm * 64;
    const int nbase = bc * 128 + wn * 64;
    const int rq = lane >> 2;
    const int cq = (lane & 3) * 2;
    float csum[8][2];
#pragma unroll
    for (int ni = 0; ni < 8; ni++) { csum[ni][0] = 0.f; csum[ni][1] = 0.f; }

#pragma unroll
    for (int ni = 0; ni < 8; ni++) {
        const int col = nbase + ni * 8 + cq;
        float f0, f1;
        if (MODE == 0) {
            f0 = cosf(aux[col] * PI_F);
            f1 = cosf(aux[col + 1] * PI_F);
        } else {
            f0 = aux[col];
            f1 = aux[col + 1];
        }
#pragma unroll
        for (int mi = 0; mi < 4; mi++) {
            const int r0 = mbase + mi * 16 + rq;
            if (MODE == 0) {
                float a0 = acc[mi][ni][0] * f0, a1 = acc[mi][ni][1] * f1;
                float a2 = acc[mi][ni][2] * f0, a3 = acc[mi][ni][3] * f1;
                csum[ni][0] += a0 + a2;
                csum[ni][1] += a1 + a3;
                *(__half2*)(g_hh + (size_t)r0 * DD + col)       = __floats2half2_rn(a0, a1);
                *(__half2*)(g_hh + (size_t)(r0 + 8) * DD + col) = __floats2half2_rn(a2, a3);
            } else {
                float2 x0 = *(const float2*)(xres + (size_t)r0 * DD + col);
                float2 x1 = *(const float2*)(xres + (size_t)(r0 + 8) * DD + col);
                float2 o0, o1;
                o0.x = acc[mi][ni][0] + f0 + x0.x; o0.y = acc[mi][ni][1] + f1 + x0.y;
                o1.x = acc[mi][ni][2] + f0 + x1.x; o1.y = acc[mi][ni][3] + f1 + x1.y;
                *(float2*)(g_heads + (size_t)r0 * DD + col) = o0;
                *(float2*)(g_heads + (size_t)(r0 + 8) * DD + col) = o1;
            }
        }
    }

    if (MODE == 0) {
        // deterministic colsum: shfl over rq lanes; stage per-wm values in
        // smem (each slot written exactly once); fixed-order sum of 4 wm.
        float* scs = (float*)sm;   // stages dead (mainloop ended with sync)
        __syncthreads();
#pragma unroll
        for (int ni = 0; ni < 8; ni++) {
            float v0 = csum[ni][0], v1 = csum[ni][1];
#pragma unroll
            for (int o = 4; o < 32; o <<= 1) {
                v0 += __shfl_xor_sync(0xffffffffu, v0, o);
                v1 += __shfl_xor_sync(0xffffffffu, v1, o);
            }
            if (rq == 0) {
                scs[wm * 128 + wn * 64 + ni * 8 + cq] = v0;
                scs[wm * 128 + wn * 64 + ni * 8 + cq + 1] = v1;
            }
        }
        __syncthreads();
        if (tid < 128) {
            float s = scs[tid];
            s += scs[128 + tid];
            s += scs[256 + tid];
            s += scs[384 + tid];
            g_part[(size_t)br * DD + bc * 128 + tid] = s;
        }
    }
}

// ---------------------------------------------------------------------------
// Fused summary-reduce + polarity + impedance.  grid=BB, 1024 threads.
// Batch b owns row tiles [b*16, b*16+16) of g_part (256-row tiles).
// ---------------------------------------------------------------------------
__global__ void polarity_fused(const float* __restrict__ pol_W,
                               const float* __restrict__ pol_b,
                               const float* __restrict__ W1,
                               const float* __restrict__ b1,
                               const float* __restrict__ W2,
                               const float* __restrict__ b2,
                               float* __restrict__ imp_out)
{
    const int b = blockIdx.x;
    const int tid = threadIdx.x;
    __shared__ float s_sum[DD];
    __shared__ float s_pol[HH * PP];

    // summary for batch b: fixed-order sum of its 16 row-tile partials
    float s = 0.f;
#pragma unroll
    for (int c = 0; c < 16; c++)
        s += g_part[(size_t)(b * 16 + c) * DD + tid];
    s_sum[tid] = s * (1.0f / (float)SS);
    __syncthreads();

    // dot: tid = h*128 + p*4 + q ; 4 lanes per (h,p), 32 k each
    const int h = tid >> 7;
    const int p = (tid >> 2) & 31;
    const int q = tid & 3;
    const float4* pw = (const float4*)(pol_W + (size_t)(h * PP + p) * KK + q * 32);
    const float* xs = s_sum + h * KK + q * 32;
    float acc = 0.f;
#pragma unroll
    for (int k4 = 0; k4 < 8; k4++) {
        float4 w = pw[k4];
        acc += xs[k4 * 4 + 0] * w.x + xs[k4 * 4 + 1] * w.y
             + xs[k4 * 4 + 2] * w.z + xs[k4 * 4 + 3] * w.w;
    }
    acc += __shfl_xor_sync(0xffffffffu, acc, 1);
    acc += __shfl_xor_sync(0xffffffffu, acc, 2);
    if (q == 0) s_pol[h * PP + p] = tanhf(acc + pol_b[h * PP + p]);
    __syncthreads();

    // normalize: warp w = head w
    const int wid = tid >> 5, lane = tid & 31;
    if (wid < HH) {
        float pv = s_pol[wid * PP + lane];
        float ss2 = pv * pv;
#pragma unroll
        for (int o = 16; o; o >>= 1) ss2 += __shfl_xor_sync(0xffffffffu, ss2, o);
        s_pol[wid * PP + lane] = pv / fmaxf(sqrtf(ss2), 1e-12f);
    }
    __syncthreads();

    // impedance: 64 (i,j) pairs
    if (tid < HH * HH) {
        const int i = tid >> 3;
        const int j = tid & 7;
        float d = 0.f;
#pragma unroll
        for (int pp = 0; pp < PP; pp++) d += s_pol[i * PP + pp] * s_pol[j * PP + pp];

        float sum2 = b2[0];
#pragma unroll
        for (int c = 0; c < 16; c++) {
            float z = d * W1[c] + b1[c];
            float g = 0.5f * z * (1.f + erff(z * 0.70710678118654752f));
            sum2 += g * W2[c];
        }
        float imp = (sum2 > 0.f) ? sum2 + log1pf(expf(-sum2)) : log1pf(expf(sum2));
        if (i == j) imp = 0.f;
        imp_out[b * 64 + tid] = imp;
        g_coef[b * 64 + tid] = (i == j) ? 0.f : 0.1f / (1.f + imp);
    }
}

// ---------------------------------------------------------------------------
// Cross-head mixing with causal scale: fp16 in (g_hh) -> fp16 out (g_mh).
// Vectorized __half2; 2 rows per 128-thread block.
// ---------------------------------------------------------------------------
__global__ void mixing_kernel(const int* __restrict__ causal)
{
    const int blk = blockIdx.x;         // 0..8191
    const int tid = threadIdx.x;        // 0..127
    const int r = tid >> 6;             // row within block
    const int k2 = tid & 63;            // half2 index within head
    const int bs = blk * 2 + r;
    const int b = blk >> 11;            // both rows share batch (4096 even)
    const int s = bs & (SS - 1);

    __shared__ float sc[HH * HH];
    if (tid < HH * HH) sc[tid] = g_coef[b * 64 + tid];
    __syncthreads();

    const __half2* row = (const __half2*)(g_hh + (size_t)bs * DD);
    float vx[HH], vy[HH];
#pragma unroll
    for (int j = 0; j < HH; j++) {
        float2 f = __half22float2(row[j * 64 + k2]);
        vx[j] = f.x; vy[j] = f.y;
    }

    const float scale = (*causal) ? (float)(s + 1) * (1.0f / (float)SS) : 1.0f;

    __half2* orow = (__half2*)(g_mh + (size_t)bs * DD);
#pragma unroll
    for (int i = 0; i < HH; i++) {
        float tx = 0.f, ty = 0.f;
#pragma unroll
        for (int j = 0; j < HH; j++) {
            tx += sc[i * 8 + j] * vx[j];
            ty += sc[i * 8 + j] * vy[j];
        }
        orow[i * 64 + k2] = __floats2half2_rn(vx[i] + scale * tx, vy[i] + scale * ty);
    }
}

// ---------------------------------------------------------------------------
// LayerNorm over D (y lives in g_heads after GEMM2)
// ---------------------------------------------------------------------------
__global__ void layernorm_kernel(const float* __restrict__ gamma,
                                 const float* __restrict__ beta,
                                 float* __restrict__ out)
{
    const int row = blockIdx.x;
    const int t = threadIdx.x;          // 0..255
    const float4 v = ((const float4*)(g_heads + (size_t)row * DD))[t];
    float s  = v.x + v.y + v.z + v.w;
    float s2 = v.x * v.x + v.y * v.y + v.z * v.z + v.w * v.w;

#pragma unroll
    for (int o = 16; o; o >>= 1) {
        s  += __shfl_xor_sync(0xffffffffu, s, o);
        s2 += __shfl_xor_sync(0xffffffffu, s2, o);
    }
    __shared__ float sh[8], sh2[8];
    const int w = t >> 5, lane = t & 31;
    if (lane == 0) { sh[w] = s; sh2[w] = s2; }
    __syncthreads();
    if (w == 0) {
        s  = (lane < 8) ? sh[lane]  : 0.f;
        s2 = (lane < 8) ? sh2[lane] : 0.f;
#pragma unroll
        for (int o = 4; o; o >>= 1) {
            s  += __shfl_xor_sync(0xffffffffu, s, o);
            s2 += __shfl_xor_sync(0xffffffffu, s2, o);
        }
        if (lane == 0) { sh[0] = s; sh2[0] = s2; }
    }
    __syncthreads();
    const float mu  = sh[0] * (1.f / (float)DD);
    const float var = sh2[0] * (1.f / (float)DD) - mu * mu;
    const float inv = rsqrtf(var + 1e-5f);

    const float4 g4 = ((const float4*)gamma)[t];
    const float4 b4 = ((const float4*)beta)[t];
    float4 o4;
    o4.x = (v.x - mu) * inv * g4.x + b4.x;
    o4.y = (v.y - mu) * inv * g4.y + b4.y;
    o4.z = (v.z - mu) * inv * g4.z + b4.z;
    o4.w = (v.w - mu) * inv * g4.w + b4.w;
    ((float4*)(out + (size_t)row * DD))[t] = o4;
}

// ---------------------------------------------------------------------------
extern "C" void kernel_launch(void* const* d_in, const int* in_sizes, int n_in,
                              void* d_out, int out_size)
{
    const float* x      = (const float*)d_in[0];   // (B,S,D)
    const float* W_proj = (const float*)d_in[1];   // (H,K,D) -> (1024,1024)
    const float* freqs  = (const float*)d_in[2];   // (H,K) -> 1024
    const float* pol_W  = (const float*)d_in[3];
    const float* pol_b  = (const float*)d_in[4];
    const float* imp_W1 = (const float*)d_in[5];
    const float* imp_b1 = (const float*)d_in[6];
    const float* imp_W2 = (const float*)d_in[7];
    const float* imp_b2 = (const float*)d_in[8];
    const float* out_W  = (const float*)d_in[9];
    const float* out_b  = (const float*)d_in[10];
    const float* ln_g   = (const float*)d_in[11];
    const float* ln_b   = (const float*)d_in[12];
    const int*   causal = (const int*)d_in[13];

    float* out = (float*)d_out;
    float* imp_out = out + (out_size - BB * HH * HH);  // impedance tail

    cudaFuncSetAttribute(gemm_mma<0>, cudaFuncAttributeMaxDynamicSharedMemorySize, GEMM_SMEM);
    cudaFuncSetAttribute(gemm_mma<1>, cudaFuncAttributeMaxDynamicSharedMemorySize, GEMM_SMEM);

    dim3 ggrid(DD / 128, NROW / 256);  // (8, 64)

    // 0) fp16 conversions: x, W_proj, out_W (one launch)
    convert_all<<<NBX + 2 * NBW, 256>>>(x, W_proj, out_W);
    // 1) heads = (x @ W_proj^T) * cos(freq*pi) -> g_hh (fp16), colsums -> g_part
    gemm_mma<0><<<ggrid, 256, GEMM_SMEM>>>(x, freqs);
    // 2) summary reduce + pol / impedance / coef (fused, one launch)
    polarity_fused<<<BB, 1024>>>(pol_W, pol_b, imp_W1, imp_b1, imp_W2, imp_b2, imp_out);
    // 3) cross-head mixing with causal scale     -> g_mh (fp16, vectorized)
    mixing_kernel<<<NROW / 2, 128>>>(causal);
    // 4) y = mixed @ out_W^T + out_b + x         -> g_heads (fp32)
    gemm_mma<1><<<ggrid, 256, GEMM_SMEM>>>(x, out_b);
    // 5) LayerNorm -> d_out
    layernorm_kernel<<<NROW, 256>>>(ln_g, ln_b, out);
}